// round 6
// baseline (speedup 1.0000x reference)
#include <cuda_runtime.h>
#include <cstdint>

// ---------------------------------------------------------------------------
// MultitaskLoss fused reduction — cp.async staged pipeline.
// Persistent 148 CTAs x 512 thr, 3-stage smem pipeline, 512-sample tiles.
// All GMEM traffic is dense 16B cp.async chunks (no wavefront amplification,
// latency hidden by 186KB of copies in flight per SM). Compute reads smem
// with a padded (80B-row) ps layout -> bank-conflict-free.
// ---------------------------------------------------------------------------

#define NTHR   512
#define NBLK   148
#define TILE   512
#define STAGES 3
#define WARPS_PER_BLK (NTHR / 32)

// ---- per-stage smem layout (bytes) ----
#define PS_ROW      80                     // 64B data + 16B pad (conflict-free)
#define PS_OFF      0
#define PT_OFF      (PS_OFF + TILE * PS_ROW)   // 40960
#define TT_OFF      (PT_OFF + TILE * 16)       // 49152
#define PB_OFF      (TT_OFF + TILE * 16)       // 57344
#define TB_OFF      (PB_OFF + TILE * 4)        // 59392
#define LBL_OFF     (TB_OFF + TILE * 4)        // 61440
#define STAGE_BYTES (LBL_OFF + TILE * 4)       // 63488
#define SMEM_BYTES  (STAGES * STAGE_BYTES)     // 190464

__device__ float g_part[5 * NBLK];
__device__ unsigned int g_count;     // zero-init; reset by last block

__device__ __forceinline__ float softplusf(float x) {
    return fmaxf(x, 0.0f) + __logf(1.0f + __expf(-fabsf(x)));
}

__device__ __forceinline__ float pick4(float4 v, int j) {
    float r = v.x;
    r = (j == 1) ? v.y : r;
    r = (j == 2) ? v.z : r;
    r = (j == 3) ? v.w : r;
    return r;
}

__device__ __forceinline__ void cp16(uint32_t dst_smem, const void* src) {
    asm volatile("cp.async.cg.shared.global [%0], [%1], 16;"
                 :: "r"(dst_smem), "l"(src));
}
__device__ __forceinline__ void cp_commit() {
    asm volatile("cp.async.commit_group;");
}
__device__ __forceinline__ void cp_wait() {          // allow STAGES-1 pending
    asm volatile("cp.async.wait_group %0;" :: "n"(STAGES - 1));
}

__device__ __forceinline__ void issue_tile(
    uint32_t sb,                 // smem stage base (shared addr space)
    long tile, int tid,
    const char* ps, const char* pt, const char* tt,
    const char* pb, const char* tb, const char* lbl)
{
    const char* ps_src = ps + tile * (TILE * 64L);
    #pragma unroll
    for (int k = 0; k < 4; k++) {            // 2048 chunks of 16B for ps
        int c = tid + NTHR * k;
        int sample = c >> 2, sub = c & 3;
        cp16(sb + PS_OFF + sample * PS_ROW + sub * 16, ps_src + c * 16L);
    }
    cp16(sb + PT_OFF + tid * 16, pt + tile * (TILE * 16L) + tid * 16L);
    cp16(sb + TT_OFF + tid * 16, tt + tile * (TILE * 16L) + tid * 16L);
    if (tid < TILE * 4 / 16) {               // 128 chunks each
        cp16(sb + PB_OFF  + tid * 16, pb  + tile * (TILE * 4L) + tid * 16L);
        cp16(sb + TB_OFF  + tid * 16, tb  + tile * (TILE * 4L) + tid * 16L);
        cp16(sb + LBL_OFF + tid * 16, lbl + tile * (TILE * 4L) + tid * 16L);
    }
}

__global__ void __launch_bounds__(NTHR, 1)
mtl_pipe_kernel(const float* __restrict__ pb,    // [B]    y_pred_binary
                const float* __restrict__ pt,    // [B,4]  y_pred_type
                const float* __restrict__ ps,    // [B,16] y_pred_source
                const float* __restrict__ tb,    // [B]    y_true_binary
                const float* __restrict__ tt,    // [B,4]  y_true_type
                const int*   __restrict__ lbl,   // [B]    y_true_source
                float* __restrict__ out,
                int B)
{
    extern __shared__ char smem[];
    const uint32_t sb0 = (uint32_t)__cvta_generic_to_shared(smem);

    const int tid = threadIdx.x;
    const int cta = blockIdx.x;
    const int ntiles = B / TILE;

    const char* psc = (const char*)ps;
    const char* ptc = (const char*)pt;
    const char* ttc = (const char*)tt;
    const char* pbc = (const char*)pb;
    const char* tbc = (const char*)tb;
    const char* lbc = (const char*)lbl;

    // ---- prologue: fill the pipeline ----
    #pragma unroll
    for (int p = 0; p < STAGES; p++) {
        long tile = cta + (long)NBLK * p;
        if (tile < ntiles)
            issue_tile(sb0 + p * STAGE_BYTES, tile, tid, psc, ptc, ttc, pbc, tbc, lbc);
        cp_commit();
    }

    float s_b = 0.f, s_t = 0.f, s_ce = 0.f, s_ab = 0.f, s_ac = 0.f;

    int stage = 0;
    for (long tile = cta; tile < ntiles; tile += NBLK) {
        cp_wait();
        __syncthreads();

        const char* st = smem + stage * STAGE_BYTES;

        // ---- compute: one sample per thread, all from smem ----
        float  xb = *(const float*)(st + PB_OFF + tid * 4);
        float  yb = *(const float*)(st + TB_OFF + tid * 4);
        float4 xt = *(const float4*)(st + PT_OFF + tid * 16);
        float4 yt = *(const float4*)(st + TT_OFF + tid * 16);
        const float4* pr = (const float4*)(st + PS_OFF + tid * PS_ROW);
        float4 a = pr[0], b = pr[1], c = pr[2], d = pr[3];
        int    l  = *(const int*)(st + LBL_OFF + tid * 4);

        s_b += softplusf(xb) - yb * xb;
        s_t += (softplusf(xt.x) - yt.x * xt.x)
             + (softplusf(xt.y) - yt.y * xt.y)
             + (softplusf(xt.z) - yt.z * xt.z)
             + (softplusf(xt.w) - yt.w * xt.w);
        bool tc = (xt.x >= 0.f) | (xt.y >= 0.f) | (xt.z >= 0.f) | (xt.w >= 0.f);

        float m = fmaxf(
            fmaxf(fmaxf(fmaxf(a.x, a.y), fmaxf(a.z, a.w)),
                  fmaxf(fmaxf(b.x, b.y), fmaxf(b.z, b.w))),
            fmaxf(fmaxf(fmaxf(c.x, c.y), fmaxf(c.z, c.w)),
                  fmaxf(fmaxf(d.x, d.y), fmaxf(d.z, d.w))));

        float se = __expf(a.x - m) + __expf(a.y - m) + __expf(a.z - m) + __expf(a.w - m)
                 + __expf(b.x - m) + __expf(b.y - m) + __expf(b.z - m) + __expf(b.w - m)
                 + __expf(c.x - m) + __expf(c.y - m) + __expf(c.z - m) + __expf(c.w - m)
                 + __expf(d.x - m) + __expf(d.y - m) + __expf(d.z - m) + __expf(d.w - m);

        float4 v = (l < 8) ? ((l < 4) ? a : b) : ((l < 12) ? c : d);
        s_ce += m + __logf(se) - pick4(v, l & 3);

        bool bc = (xb >= 0.f);              // sigmoid(x) >= 0.5 <=> x >= 0
        bool sc = (a.x < m);                // argmax > 0 (first-occurrence)
        s_ab += (bc != tc) ? 1.f : 0.f;
        s_ac += (bc != sc) ? 1.f : 0.f;

        __syncthreads();                    // everyone done with this buffer

        long next = tile + (long)NBLK * STAGES;
        if (next < ntiles)
            issue_tile(sb0 + stage * STAGE_BYTES, next, tid, psc, ptc, ttc, pbc, tbc, lbc);
        cp_commit();

        stage = (stage == STAGES - 1) ? 0 : stage + 1;
    }

    // ---- remainder samples (B % TILE) — direct gmem, CTA 0 only ----
    if (cta == 0) {
        for (int i = ntiles * TILE + tid; i < B; i += NTHR) {
            float  xb = pb[i];
            float  yb = tb[i];
            const float4* xt4 = (const float4*)(pt + 4L * i);
            const float4* yt4 = (const float4*)(tt + 4L * i);
            float4 xt = *xt4, yt = *yt4;
            s_b += softplusf(xb) - yb * xb;
            s_t += (softplusf(xt.x) - yt.x * xt.x)
                 + (softplusf(xt.y) - yt.y * xt.y)
                 + (softplusf(xt.z) - yt.z * xt.z)
                 + (softplusf(xt.w) - yt.w * xt.w);
            bool tc = (xt.x >= 0.f) | (xt.y >= 0.f) | (xt.z >= 0.f) | (xt.w >= 0.f);

            const float4* pr = (const float4*)(ps + 16L * i);
            float4 a = pr[0], b = pr[1], c = pr[2], d = pr[3];
            float m = fmaxf(
                fmaxf(fmaxf(fmaxf(a.x, a.y), fmaxf(a.z, a.w)),
                      fmaxf(fmaxf(b.x, b.y), fmaxf(b.z, b.w))),
                fmaxf(fmaxf(fmaxf(c.x, c.y), fmaxf(c.z, c.w)),
                      fmaxf(fmaxf(d.x, d.y), fmaxf(d.z, d.w))));
            float se = __expf(a.x-m)+__expf(a.y-m)+__expf(a.z-m)+__expf(a.w-m)
                     + __expf(b.x-m)+__expf(b.y-m)+__expf(b.z-m)+__expf(b.w-m)
                     + __expf(c.x-m)+__expf(c.y-m)+__expf(c.z-m)+__expf(c.w-m)
                     + __expf(d.x-m)+__expf(d.y-m)+__expf(d.z-m)+__expf(d.w-m);
            int l = lbl[i];
            float4 v = (l < 8) ? ((l < 4) ? a : b) : ((l < 12) ? c : d);
            s_ce += m + __logf(se) - pick4(v, l & 3);
            bool bc = (xb >= 0.f);
            bool sc = (a.x < m);
            s_ab += (bc != tc) ? 1.f : 0.f;
            s_ac += (bc != sc) ? 1.f : 0.f;
        }
    }

    // ---- block reduction ----
    #pragma unroll
    for (int o = 16; o; o >>= 1) {
        s_b  += __shfl_down_sync(0xffffffffu, s_b,  o);
        s_t  += __shfl_down_sync(0xffffffffu, s_t,  o);
        s_ce += __shfl_down_sync(0xffffffffu, s_ce, o);
        s_ab += __shfl_down_sync(0xffffffffu, s_ab, o);
        s_ac += __shfl_down_sync(0xffffffffu, s_ac, o);
    }

    __shared__ float red[5][WARPS_PER_BLK];
    int warp = tid >> 5;
    int lane = tid & 31;
    if (lane == 0) {
        red[0][warp] = s_b;  red[1][warp] = s_t;  red[2][warp] = s_ce;
        red[3][warp] = s_ab; red[4][warp] = s_ac;
    }
    __syncthreads();

    if (tid == 0) {
        float t0=0.f, t1=0.f, t2=0.f, t3=0.f, t4=0.f;
        #pragma unroll
        for (int k = 0; k < WARPS_PER_BLK; k++) {
            t0 += red[0][k]; t1 += red[1][k]; t2 += red[2][k];
            t3 += red[3][k]; t4 += red[4][k];
        }
        g_part[0 * NBLK + cta] = t0;
        g_part[1 * NBLK + cta] = t1;
        g_part[2 * NBLK + cta] = t2;
        g_part[3 * NBLK + cta] = t3;
        g_part[4 * NBLK + cta] = t4;
    }

    // ---- last-block finalize ----
    __shared__ bool is_last;
    if (tid == 0) {
        __threadfence();
        unsigned int done = atomicAdd(&g_count, 1u);
        is_last = (done == (unsigned int)(gridDim.x - 1));
    }
    __syncthreads();
    if (!is_last) return;

    __threadfence();

    if (tid < 32) {                         // 148 partials -> one warp
        double acc[5] = {0.0, 0.0, 0.0, 0.0, 0.0};
        for (int bx = tid; bx < NBLK; bx += 32) {
            #pragma unroll
            for (int k = 0; k < 5; k++)
                acc[k] += (double)g_part[k * NBLK + bx];
        }
        #pragma unroll
        for (int o = 16; o; o >>= 1) {
            #pragma unroll
            for (int k = 0; k < 5; k++)
                acc[k] += __shfl_down_sync(0xffffffffu, acc[k], o);
        }
        if (tid == 0) {
            double Bd = (double)B;
            double loss = acc[0] / Bd            // binary BCE mean
                        + acc[1] / (Bd * 4.0)    // type BCE mean over B*T
                        + acc[2] / Bd            // CE mean
                        + acc[3] / Bd            // cons_ab mean
                        + acc[4] / Bd;           // cons_ac mean
            out[0] = (float)loss;
            g_count = 0;                         // reset for next replay
        }
    }
}

extern "C" void kernel_launch(void* const* d_in, const int* in_sizes, int n_in,
                              void* d_out, int out_size)
{
    const float* pb  = (const float*)d_in[0];   // y_pred_binary  [B]
    const float* pt  = (const float*)d_in[1];   // y_pred_type    [B,4]
    const float* ps  = (const float*)d_in[2];   // y_pred_source  [B,16]
    const float* tb  = (const float*)d_in[3];   // y_true_binary  [B]
    const float* tt  = (const float*)d_in[4];   // y_true_type    [B,4]
    const int*   lbl = (const int*)  d_in[5];   // y_true_source  [B]
    float* out = (float*)d_out;

    int B = in_sizes[0];

    cudaFuncSetAttribute(mtl_pipe_kernel,
                         cudaFuncAttributeMaxDynamicSharedMemorySize, SMEM_BYTES);
    mtl_pipe_kernel<<<NBLK, NTHR, SMEM_BYTES>>>(pb, pt, ps, tb, tt, lbl, out, B);
}

// round 9
// speedup vs baseline: 1.1422x; 1.1422x over previous
#include <cuda_runtime.h>
#include <cstdint>

// ---------------------------------------------------------------------------
// MultitaskLoss fused reduction — TMA bulk-copy (UBLKCP) pipeline.
// 148 persistent CTAs x 512 thr. Per 512-sample tile, ONE thread issues 6
// cp.async.bulk copies (55,296 B total) completing on an mbarrier; 4-stage
// ring in 221 KB smem. Zero per-thread global requests -> no L1tex wavefront
// overhead; the TMA engine streams at line rate. Compute unchanged.
// ---------------------------------------------------------------------------

#define NTHR   512
#define NBLK   148
#define TILE   512
#define STAGES 4
#define WARPS_PER_BLK (NTHR / 32)

// ---- smem layout ----
#define MBAR_OFF    0                 // 4 mbarriers * 8 B
#define STAGE_BASE  128
#define PS_OFF      0                 // 512 * 64 B
#define PT_OFF      32768             // 512 * 16 B
#define TT_OFF      40960             // 512 * 16 B
#define PB_OFF      49152             // 512 * 4 B
#define TB_OFF      51200
#define LBL_OFF     53248
#define STAGE_BYTES 55296             // == total bytes per tile (expect_tx)
#define SMEM_BYTES  (STAGE_BASE + STAGES * STAGE_BYTES)   // 221312

__device__ float g_part[5 * NBLK];
__device__ unsigned int g_count;      // zero-init; reset by last block

__device__ __forceinline__ float softplusf(float x) {
    return fmaxf(x, 0.0f) + __logf(1.0f + __expf(-fabsf(x)));
}

__device__ __forceinline__ float pick4(float4 v, int j) {
    float r = v.x;
    r = (j == 1) ? v.y : r;
    r = (j == 2) ? v.z : r;
    r = (j == 3) ? v.w : r;
    return r;
}

__device__ __forceinline__ void mbar_init(uint32_t mbar, uint32_t count) {
    asm volatile("mbarrier.init.shared.b64 [%0], %1;"
                 :: "r"(mbar), "r"(count) : "memory");
}
__device__ __forceinline__ void mbar_expect_tx(uint32_t mbar, uint32_t bytes) {
    asm volatile("mbarrier.arrive.expect_tx.shared.b64 _, [%0], %1;"
                 :: "r"(mbar), "r"(bytes) : "memory");
}
__device__ __forceinline__ void mbar_wait(uint32_t mbar, uint32_t parity) {
    asm volatile(
        "{\n\t"
        ".reg .pred P;\n\t"
        "WAIT_%=:\n\t"
        "mbarrier.try_wait.parity.acquire.cta.shared::cta.b64 P, [%0], %1, 0x989680;\n\t"
        "@P bra WAIT_DONE_%=;\n\t"
        "bra.uni WAIT_%=;\n\t"
        "WAIT_DONE_%=:\n\t"
        "}"
        :: "r"(mbar), "r"(parity) : "memory");
}
__device__ __forceinline__ void bulk_cp(uint32_t dst, const void* src,
                                        uint32_t bytes, uint32_t mbar) {
    asm volatile(
        "cp.async.bulk.shared::cta.global.mbarrier::complete_tx::bytes "
        "[%0], [%1], %2, [%3];"
        :: "r"(dst), "l"(src), "r"(bytes), "r"(mbar) : "memory");
}

// thread 0 only: arm the barrier and issue the whole tile as 6 bulk copies
__device__ __forceinline__ void issue_tile(
    uint32_t st, uint32_t mbar, long tile,
    const char* ps, const char* pt, const char* tt,
    const char* pb, const char* tb, const char* lb)
{
    mbar_expect_tx(mbar, STAGE_BYTES);
    bulk_cp(st + PS_OFF,  ps + tile * 32768L, 32768, mbar);
    bulk_cp(st + PT_OFF,  pt + tile * 8192L,  8192,  mbar);
    bulk_cp(st + TT_OFF,  tt + tile * 8192L,  8192,  mbar);
    bulk_cp(st + PB_OFF,  pb + tile * 2048L,  2048,  mbar);
    bulk_cp(st + TB_OFF,  tb + tile * 2048L,  2048,  mbar);
    bulk_cp(st + LBL_OFF, lb + tile * 2048L,  2048,  mbar);
}

__global__ void __launch_bounds__(NTHR, 1)
mtl_bulk_kernel(const float* __restrict__ pb,    // [B]    y_pred_binary
                const float* __restrict__ pt,    // [B,4]  y_pred_type
                const float* __restrict__ ps,    // [B,16] y_pred_source
                const float* __restrict__ tb,    // [B]    y_true_binary
                const float* __restrict__ tt,    // [B,4]  y_true_type
                const int*   __restrict__ lbl,   // [B]    y_true_source
                float* __restrict__ out,
                int B)
{
    extern __shared__ char smem[];
    const uint32_t sb = (uint32_t)__cvta_generic_to_shared(smem);

    const int tid = threadIdx.x;
    const int cta = blockIdx.x;
    const int ntiles = B / TILE;

    const char* psc = (const char*)ps;
    const char* ptc = (const char*)pt;
    const char* ttc = (const char*)tt;
    const char* pbc = (const char*)pb;
    const char* tbc = (const char*)tb;
    const char* lbc = (const char*)lbl;

    if (tid == 0) {
        #pragma unroll
        for (int s = 0; s < STAGES; s++)
            mbar_init(sb + MBAR_OFF + s * 8, 1);
        asm volatile("fence.proxy.async.shared::cta;" ::: "memory");
    }
    __syncthreads();

    // ---- prologue: fill the ring ----
    if (tid == 0) {
        #pragma unroll
        for (int p = 0; p < STAGES; p++) {
            long tile = cta + (long)NBLK * p;
            if (tile < ntiles)
                issue_tile(sb + STAGE_BASE + p * STAGE_BYTES,
                           sb + MBAR_OFF + p * 8, tile,
                           psc, ptc, ttc, pbc, tbc, lbc);
        }
    }

    float s_b = 0.f, s_t = 0.f, s_ce = 0.f, s_ab = 0.f, s_ac = 0.f;

    long k = 0;
    for (long tile = cta; tile < ntiles; tile += NBLK, k++) {
        const int stage  = (int)(k & (STAGES - 1));
        const uint32_t parity = (uint32_t)((k >> 2) & 1);
        const uint32_t mbar = sb + MBAR_OFF + stage * 8;

        mbar_wait(mbar, parity);

        const char* st = smem + STAGE_BASE + stage * STAGE_BYTES;

        // ---- compute: one sample per thread, all from smem ----
        float  xb = *(const float*)(st + PB_OFF + tid * 4);
        float  yb = *(const float*)(st + TB_OFF + tid * 4);
        float4 xt = *(const float4*)(st + PT_OFF + tid * 16);
        float4 yt = *(const float4*)(st + TT_OFF + tid * 16);
        const float4* pr = (const float4*)(st + PS_OFF + tid * 64);
        float4 a = pr[0], b = pr[1], c = pr[2], d = pr[3];
        int    l  = *(const int*)(st + LBL_OFF + tid * 4);

        s_b += softplusf(xb) - yb * xb;
        s_t += (softplusf(xt.x) - yt.x * xt.x)
             + (softplusf(xt.y) - yt.y * xt.y)
             + (softplusf(xt.z) - yt.z * xt.z)
             + (softplusf(xt.w) - yt.w * xt.w);
        bool tc = (xt.x >= 0.f) | (xt.y >= 0.f) | (xt.z >= 0.f) | (xt.w >= 0.f);

        float m = fmaxf(
            fmaxf(fmaxf(fmaxf(a.x, a.y), fmaxf(a.z, a.w)),
                  fmaxf(fmaxf(b.x, b.y), fmaxf(b.z, b.w))),
            fmaxf(fmaxf(fmaxf(c.x, c.y), fmaxf(c.z, c.w)),
                  fmaxf(fmaxf(d.x, d.y), fmaxf(d.z, d.w))));

        float se = __expf(a.x - m) + __expf(a.y - m) + __expf(a.z - m) + __expf(a.w - m)
                 + __expf(b.x - m) + __expf(b.y - m) + __expf(b.z - m) + __expf(b.w - m)
                 + __expf(c.x - m) + __expf(c.y - m) + __expf(c.z - m) + __expf(c.w - m)
                 + __expf(d.x - m) + __expf(d.y - m) + __expf(d.z - m) + __expf(d.w - m);

        float4 v = (l < 8) ? ((l < 4) ? a : b) : ((l < 12) ? c : d);
        s_ce += m + __logf(se) - pick4(v, l & 3);

        bool bc = (xb >= 0.f);              // sigmoid(x) >= 0.5 <=> x >= 0
        bool sc = (a.x < m);                // argmax > 0 (first-occurrence)
        s_ab += (bc != tc) ? 1.f : 0.f;
        s_ac += (bc != sc) ? 1.f : 0.f;

        __syncthreads();                    // whole CTA done with this buffer

        if (tid == 0) {
            long next = tile + (long)NBLK * STAGES;
            if (next < ntiles)
                issue_tile(sb + STAGE_BASE + stage * STAGE_BYTES, mbar, next,
                           psc, ptc, ttc, pbc, tbc, lbc);
        }
    }

    // ---- remainder samples (B % TILE) — direct gmem, CTA 0 only ----
    if (cta == 0) {
        for (int i = ntiles * TILE + tid; i < B; i += NTHR) {
            float  xb = pb[i];
            float  yb = tb[i];
            float4 xt = *(const float4*)(pt + 4L * i);
            float4 yt = *(const float4*)(tt + 4L * i);
            s_b += softplusf(xb) - yb * xb;
            s_t += (softplusf(xt.x) - yt.x * xt.x)
                 + (softplusf(xt.y) - yt.y * xt.y)
                 + (softplusf(xt.z) - yt.z * xt.z)
                 + (softplusf(xt.w) - yt.w * xt.w);
            bool tc = (xt.x >= 0.f) | (xt.y >= 0.f) | (xt.z >= 0.f) | (xt.w >= 0.f);

            const float4* pr = (const float4*)(ps + 16L * i);
            float4 a = pr[0], b = pr[1], c = pr[2], d = pr[3];
            float m = fmaxf(
                fmaxf(fmaxf(fmaxf(a.x, a.y), fmaxf(a.z, a.w)),
                      fmaxf(fmaxf(b.x, b.y), fmaxf(b.z, b.w))),
                fmaxf(fmaxf(fmaxf(c.x, c.y), fmaxf(c.z, c.w)),
                      fmaxf(fmaxf(d.x, d.y), fmaxf(d.z, d.w))));
            float se = __expf(a.x-m)+__expf(a.y-m)+__expf(a.z-m)+__expf(a.w-m)
                     + __expf(b.x-m)+__expf(b.y-m)+__expf(b.z-m)+__expf(b.w-m)
                     + __expf(c.x-m)+__expf(c.y-m)+__expf(c.z-m)+__expf(c.w-m)
                     + __expf(d.x-m)+__expf(d.y-m)+__expf(d.z-m)+__expf(d.w-m);
            int l = lbl[i];
            float4 v = (l < 8) ? ((l < 4) ? a : b) : ((l < 12) ? c : d);
            s_ce += m + __logf(se) - pick4(v, l & 3);
            bool bc = (xb >= 0.f);
            bool sc = (a.x < m);
            s_ab += (bc != tc) ? 1.f : 0.f;
            s_ac += (bc != sc) ? 1.f : 0.f;
        }
    }

    // ---- block reduction ----
    #pragma unroll
    for (int o = 16; o; o >>= 1) {
        s_b  += __shfl_down_sync(0xffffffffu, s_b,  o);
        s_t  += __shfl_down_sync(0xffffffffu, s_t,  o);
        s_ce += __shfl_down_sync(0xffffffffu, s_ce, o);
        s_ab += __shfl_down_sync(0xffffffffu, s_ab, o);
        s_ac += __shfl_down_sync(0xffffffffu, s_ac, o);
    }

    __shared__ float red[5][WARPS_PER_BLK];
    int warp = tid >> 5;
    int lane = tid & 31;
    if (lane == 0) {
        red[0][warp] = s_b;  red[1][warp] = s_t;  red[2][warp] = s_ce;
        red[3][warp] = s_ab; red[4][warp] = s_ac;
    }
    __syncthreads();

    if (tid == 0) {
        float t0=0.f, t1=0.f, t2=0.f, t3=0.f, t4=0.f;
        #pragma unroll
        for (int j = 0; j < WARPS_PER_BLK; j++) {
            t0 += red[0][j]; t1 += red[1][j]; t2 += red[2][j];
            t3 += red[3][j]; t4 += red[4][j];
        }
        g_part[0 * NBLK + cta] = t0;
        g_part[1 * NBLK + cta] = t1;
        g_part[2 * NBLK + cta] = t2;
        g_part[3 * NBLK + cta] = t3;
        g_part[4 * NBLK + cta] = t4;
    }

    // ---- last-block finalize ----
    __shared__ bool is_last;
    if (tid == 0) {
        __threadfence();
        unsigned int done = atomicAdd(&g_count, 1u);
        is_last = (done == (unsigned int)(gridDim.x - 1));
    }
    __syncthreads();
    if (!is_last) return;

    __threadfence();

    if (tid < 32) {                        // 148 partials -> one warp
        double acc[5] = {0.0, 0.0, 0.0, 0.0, 0.0};
        for (int bx = tid; bx < NBLK; bx += 32) {
            #pragma unroll
            for (int q = 0; q < 5; q++)
                acc[q] += (double)g_part[q * NBLK + bx];
        }
        #pragma unroll
        for (int o = 16; o; o >>= 1) {
            #pragma unroll
            for (int q = 0; q < 5; q++)
                acc[q] += __shfl_down_sync(0xffffffffu, acc[q], o);
        }
        if (tid == 0) {
            double Bd = (double)B;
            double loss = acc[0] / Bd            // binary BCE mean
                        + acc[1] / (Bd * 4.0)    // type BCE mean over B*T
                        + acc[2] / Bd            // CE mean
                        + acc[3] / Bd            // cons_ab mean
                        + acc[4] / Bd;           // cons_ac mean
            out[0] = (float)loss;
            g_count = 0;                         // reset for next replay
        }
    }
}

extern "C" void kernel_launch(void* const* d_in, const int* in_sizes, int n_in,
                              void* d_out, int out_size)
{
    const float* pb  = (const float*)d_in[0];   // y_pred_binary  [B]
    const float* pt  = (const float*)d_in[1];   // y_pred_type    [B,4]
    const float* ps  = (const float*)d_in[2];   // y_pred_source  [B,16]
    const float* tb  = (const float*)d_in[3];   // y_true_binary  [B]
    const float* tt  = (const float*)d_in[4];   // y_true_type    [B,4]
    const int*   lbl = (const int*)  d_in[5];   // y_true_source  [B]
    float* out = (float*)d_out;

    int B = in_sizes[0];

    cudaFuncSetAttribute(mtl_bulk_kernel,
                         cudaFuncAttributeMaxDynamicSharedMemorySize, SMEM_BYTES);
    mtl_bulk_kernel<<<NBLK, NTHR, SMEM_BYTES>>>(pb, pt, ps, tb, tt, lbl, out, B);
}